// round 8
// baseline (speedup 1.0000x reference)
#include <cuda_runtime.h>
#include <cuda_bf16.h>
#include <cstdint>

// Problem constants (fixed by the reference generator)
#define F_DIM 16
#define B_GRAPHS 8
#define NVALS 9               // base + 8 segment dots
#define ACC_BLOCKS 888        // 148 SMs x 6 blocks -> single persistent wave
#define ACC_THREADS 256

// Per-block partials, transposed: g_partials[k][block]. Fully rewritten each
// launch -> no zeroing needed.
__device__ float g_partials[NVALS][ACC_BLOCKS];
// Ticket counter: starts 0 at module load; last block resets it to 0 every
// launch -> deterministic across graph replays.
__device__ unsigned int g_ticket;

__global__ __launch_bounds__(ACC_THREADS, 6) void fused_kernel(
    const float* __restrict__ inp,
    const float* __restrict__ tgt,
    const int* __restrict__ batch,
    float* __restrict__ out,
    int n)
{
    float base = 0.0f;
    float dots[B_GRAPHS];
#pragma unroll
    for (int b = 0; b < B_GRAPHS; b++) dots[b] = 0.0f;

    const float4* __restrict__ inp4 = reinterpret_cast<const float4*>(inp);
    const float4* __restrict__ tgt4 = reinterpret_cast<const float4*>(tgt);

    const int total4 = n * 4;   // one float4 = quarter of a row

    // Contiguous per-block range; threads stride blockDim within it.
    // Warp still reads 512B contiguous per LDG (coalescing floor), but the
    // block walks one contiguous region -> sorted `batch` means a thread's
    // bid is constant for nearly the whole range.
    const int r_start = (int)(((long long)blockIdx.x * total4) / gridDim.x);
    const int r_end   = (int)(((long long)(blockIdx.x + 1) * total4) / gridDim.x);

    int   cur_bid = -1;     // no graph yet
    float cur_sum = 0.0f;

#pragma unroll 8
    for (int f = r_start + threadIdx.x; f < r_end; f += ACC_THREADS) {
        float4 x = __ldcs(inp4 + f);
        float4 y = __ldcs(tgt4 + f);
        int bid = __ldg(batch + (f >> 2)) & (B_GRAPHS - 1);  // quad-broadcast

        float sq = 0.0f;
        sq = fmaf(x.x, x.x, sq); sq = fmaf(x.y, x.y, sq);
        sq = fmaf(x.z, x.z, sq); sq = fmaf(x.w, x.w, sq);
        sq = fmaf(y.x, y.x, sq); sq = fmaf(y.y, y.y, sq);
        sq = fmaf(y.z, y.z, sq); sq = fmaf(y.w, y.w, sq);
        base += sq;

        float d = 0.0f;
        d = fmaf(x.x, y.x, d); d = fmaf(x.y, y.y, d);
        d = fmaf(x.z, y.z, d); d = fmaf(x.w, y.w, d);

        if (bid != cur_bid) {
            // rare: graph boundary (batch is sorted) or first iteration
            if (cur_bid >= 0) {
#pragma unroll
                for (int b = 0; b < B_GRAPHS; b++)
                    if (cur_bid == b) dots[b] += cur_sum;
            }
            cur_bid = bid;
            cur_sum = 0.0f;
        }
        cur_sum += d;
    }
    // final flush
    if (cur_bid >= 0) {
#pragma unroll
        for (int b = 0; b < B_GRAPHS; b++)
            if (cur_bid == b) dots[b] += cur_sum;
    }

    // ----- block reduce of the 9 values -----
    float vals[NVALS];
    vals[0] = base;
#pragma unroll
    for (int b = 0; b < B_GRAPHS; b++) vals[b + 1] = dots[b];

#pragma unroll
    for (int k = 0; k < NVALS; k++) {
#pragma unroll
        for (int off = 16; off > 0; off >>= 1)
            vals[k] += __shfl_down_sync(0xFFFFFFFFu, vals[k], off);
    }

    __shared__ float smem[ACC_THREADS / 32][NVALS];
    __shared__ int s_is_last;
    int warp = threadIdx.x >> 5;
    int lane = threadIdx.x & 31;
    if (lane == 0) {
#pragma unroll
        for (int k = 0; k < NVALS; k++) smem[warp][k] = vals[k];
    }
    __syncthreads();

    if (threadIdx.x == 0) {
        float o[NVALS];
#pragma unroll
        for (int k = 0; k < NVALS; k++) o[k] = smem[0][k];
#pragma unroll
        for (int w = 1; w < ACC_THREADS / 32; w++) {
#pragma unroll
            for (int k = 0; k < NVALS; k++) o[k] += smem[w][k];
        }
#pragma unroll
        for (int k = 0; k < NVALS; k++)
            g_partials[k][blockIdx.x] = o[k];

        __threadfence();
        unsigned int ticket = atomicAdd(&g_ticket, 1u);
        s_is_last = (ticket == (unsigned)(gridDim.x - 1)) ? 1 : 0;
    }
    __syncthreads();

    if (!s_is_last) return;

    // ----- last block: reduce all partials (coalesced float4 reads) -----
    __threadfence();   // acquire side of the ticket handshake
    float fv[NVALS];
#pragma unroll
    for (int k = 0; k < NVALS; k++) fv[k] = 0.0f;

    // ACC_BLOCKS = 888 floats per component (not multiple of 4 -> scalar loop)
    for (int r = threadIdx.x; r < ACC_BLOCKS; r += ACC_THREADS) {
#pragma unroll
        for (int k = 0; k < NVALS; k++)
            fv[k] += g_partials[k][r];
    }

#pragma unroll
    for (int k = 0; k < NVALS; k++) {
#pragma unroll
        for (int off = 16; off > 0; off >>= 1)
            fv[k] += __shfl_down_sync(0xFFFFFFFFu, fv[k], off);
    }

    __syncthreads();   // smem reuse
    if (lane == 0) {
#pragma unroll
        for (int k = 0; k < NVALS; k++) smem[warp][k] = fv[k];
    }
    __syncthreads();

    if (threadIdx.x == 0) {
        float acc[NVALS];
#pragma unroll
        for (int k = 0; k < NVALS; k++) acc[k] = smem[0][k];
#pragma unroll
        for (int w = 1; w < ACC_THREADS / 32; w++) {
#pragma unroll
            for (int k = 0; k < NVALS; k++) acc[k] += smem[w][k];
        }
        // min over all 2^B sign combos == base - 2 * sum_b |dot_b|
        float s = 0.0f;
#pragma unroll
        for (int b = 0; b < B_GRAPHS; b++) s += fabsf(acc[b + 1]);
        out[0] = acc[0] - 2.0f * s;
        g_ticket = 0u;   // reset for next graph replay
    }
}

extern "C" void kernel_launch(void* const* d_in, const int* in_sizes, int n_in,
                              void* d_out, int out_size)
{
    const float* inp   = (const float*)d_in[0];
    const float* tgt   = (const float*)d_in[1];
    const int*   batch = (const int*)d_in[2];
    float* out = (float*)d_out;

    int n = in_sizes[2];  // number of nodes (batch vector length)

    fused_kernel<<<ACC_BLOCKS, ACC_THREADS>>>(inp, tgt, batch, out, n);
}

// round 9
// speedup vs baseline: 1.0838x; 1.0838x over previous
#include <cuda_runtime.h>
#include <cuda_bf16.h>
#include <cstdint>

// Problem constants (fixed by the reference generator)
#define F_DIM 16
#define B_GRAPHS 8
#define NVALS 9               // base + 8 segment dots
#define ACC_BLOCKS 592        // 148 SMs x 4 blocks -> single persistent wave
#define ACC_THREADS 256

// Per-block partials, transposed: g_partials[k][block]. Fully rewritten each
// launch -> no zeroing needed.
__device__ float g_partials[NVALS][ACC_BLOCKS];
// Ticket counter: starts 0 at module load; last block resets it to 0 every
// launch -> deterministic across graph replays.
__device__ unsigned int g_ticket;

__global__ __launch_bounds__(ACC_THREADS, 4) void fused_kernel(
    const float* __restrict__ inp,
    const float* __restrict__ tgt,
    const int* __restrict__ batch,
    float* __restrict__ out,
    int n)
{
    float base = 0.0f;
    float dots[B_GRAPHS];
#pragma unroll
    for (int b = 0; b < B_GRAPHS; b++) dots[b] = 0.0f;

    const float4* __restrict__ inp4 = reinterpret_cast<const float4*>(inp);
    const float4* __restrict__ tgt4 = reinterpret_cast<const float4*>(tgt);

    const int total4 = n * 4;   // one float4 = quarter of a row
    const int T = ACC_THREADS;

    // Contiguous per-block range; warp reads 512B contiguous per LDG.
    const int r_start = (int)(((long long)blockIdx.x * total4) / gridDim.x);
    const int r_end   = (int)(((long long)(blockIdx.x + 1) * total4) / gridDim.x);

    int   cur_bid = -1;     // running-segment accumulator (batch is sorted)
    float cur_sum = 0.0f;

    int f = r_start + threadIdx.x;

    // ---- main loop: 4 iterations batched -> 8 independent LDG.128 in flight ----
    for (; f + 3 * T < r_end; f += 4 * T) {
        float4 x0 = __ldcs(inp4 + f);
        float4 x1 = __ldcs(inp4 + f + T);
        float4 x2 = __ldcs(inp4 + f + 2 * T);
        float4 x3 = __ldcs(inp4 + f + 3 * T);
        float4 y0 = __ldcs(tgt4 + f);
        float4 y1 = __ldcs(tgt4 + f + T);
        float4 y2 = __ldcs(tgt4 + f + 2 * T);
        float4 y3 = __ldcs(tgt4 + f + 3 * T);
        int b0 = __ldg(batch + (f >> 2)) & (B_GRAPHS - 1);
        int b1 = __ldg(batch + ((f + T) >> 2)) & (B_GRAPHS - 1);
        int b2 = __ldg(batch + ((f + 2 * T) >> 2)) & (B_GRAPHS - 1);
        int b3 = __ldg(batch + ((f + 3 * T) >> 2)) & (B_GRAPHS - 1);

        float sq = 0.0f;
        sq = fmaf(x0.x, x0.x, sq); sq = fmaf(x0.y, x0.y, sq);
        sq = fmaf(x0.z, x0.z, sq); sq = fmaf(x0.w, x0.w, sq);
        sq = fmaf(y0.x, y0.x, sq); sq = fmaf(y0.y, y0.y, sq);
        sq = fmaf(y0.z, y0.z, sq); sq = fmaf(y0.w, y0.w, sq);
        sq = fmaf(x1.x, x1.x, sq); sq = fmaf(x1.y, x1.y, sq);
        sq = fmaf(x1.z, x1.z, sq); sq = fmaf(x1.w, x1.w, sq);
        sq = fmaf(y1.x, y1.x, sq); sq = fmaf(y1.y, y1.y, sq);
        sq = fmaf(y1.z, y1.z, sq); sq = fmaf(y1.w, y1.w, sq);
        sq = fmaf(x2.x, x2.x, sq); sq = fmaf(x2.y, x2.y, sq);
        sq = fmaf(x2.z, x2.z, sq); sq = fmaf(x2.w, x2.w, sq);
        sq = fmaf(y2.x, y2.x, sq); sq = fmaf(y2.y, y2.y, sq);
        sq = fmaf(y2.z, y2.z, sq); sq = fmaf(y2.w, y2.w, sq);
        sq = fmaf(x3.x, x3.x, sq); sq = fmaf(x3.y, x3.y, sq);
        sq = fmaf(x3.z, x3.z, sq); sq = fmaf(x3.w, x3.w, sq);
        sq = fmaf(y3.x, y3.x, sq); sq = fmaf(y3.y, y3.y, sq);
        sq = fmaf(y3.z, y3.z, sq); sq = fmaf(y3.w, y3.w, sq);
        base += sq;

        float d0 = 0.0f, d1 = 0.0f, d2 = 0.0f, d3 = 0.0f;
        d0 = fmaf(x0.x, y0.x, d0); d0 = fmaf(x0.y, y0.y, d0);
        d0 = fmaf(x0.z, y0.z, d0); d0 = fmaf(x0.w, y0.w, d0);
        d1 = fmaf(x1.x, y1.x, d1); d1 = fmaf(x1.y, y1.y, d1);
        d1 = fmaf(x1.z, y1.z, d1); d1 = fmaf(x1.w, y1.w, d1);
        d2 = fmaf(x2.x, y2.x, d2); d2 = fmaf(x2.y, y2.y, d2);
        d2 = fmaf(x2.z, y2.z, d2); d2 = fmaf(x2.w, y2.w, d2);
        d3 = fmaf(x3.x, y3.x, d3); d3 = fmaf(x3.y, y3.y, d3);
        d3 = fmaf(x3.z, y3.z, d3); d3 = fmaf(x3.w, y3.w, d3);

        // running-segment accumulate (bid changes are rare: batch is sorted)
        if (b0 != cur_bid) {
            if (cur_bid >= 0) {
#pragma unroll
                for (int b = 0; b < B_GRAPHS; b++)
                    if (cur_bid == b) dots[b] += cur_sum;
            }
            cur_bid = b0; cur_sum = 0.0f;
        }
        cur_sum += d0;
        if (b1 != cur_bid) {
#pragma unroll
            for (int b = 0; b < B_GRAPHS; b++)
                if (cur_bid == b) dots[b] += cur_sum;
            cur_bid = b1; cur_sum = 0.0f;
        }
        cur_sum += d1;
        if (b2 != cur_bid) {
#pragma unroll
            for (int b = 0; b < B_GRAPHS; b++)
                if (cur_bid == b) dots[b] += cur_sum;
            cur_bid = b2; cur_sum = 0.0f;
        }
        cur_sum += d2;
        if (b3 != cur_bid) {
#pragma unroll
            for (int b = 0; b < B_GRAPHS; b++)
                if (cur_bid == b) dots[b] += cur_sum;
            cur_bid = b3; cur_sum = 0.0f;
        }
        cur_sum += d3;
    }

    // ---- tail: single-step ----
    for (; f < r_end; f += T) {
        float4 x = __ldcs(inp4 + f);
        float4 y = __ldcs(tgt4 + f);
        int bid = __ldg(batch + (f >> 2)) & (B_GRAPHS - 1);

        float sq = 0.0f;
        sq = fmaf(x.x, x.x, sq); sq = fmaf(x.y, x.y, sq);
        sq = fmaf(x.z, x.z, sq); sq = fmaf(x.w, x.w, sq);
        sq = fmaf(y.x, y.x, sq); sq = fmaf(y.y, y.y, sq);
        sq = fmaf(y.z, y.z, sq); sq = fmaf(y.w, y.w, sq);
        base += sq;

        float d = 0.0f;
        d = fmaf(x.x, y.x, d); d = fmaf(x.y, y.y, d);
        d = fmaf(x.z, y.z, d); d = fmaf(x.w, y.w, d);

        if (bid != cur_bid) {
            if (cur_bid >= 0) {
#pragma unroll
                for (int b = 0; b < B_GRAPHS; b++)
                    if (cur_bid == b) dots[b] += cur_sum;
            }
            cur_bid = bid; cur_sum = 0.0f;
        }
        cur_sum += d;
    }
    // final flush
    if (cur_bid >= 0) {
#pragma unroll
        for (int b = 0; b < B_GRAPHS; b++)
            if (cur_bid == b) dots[b] += cur_sum;
    }

    // ----- block reduce of the 9 values -----
    float vals[NVALS];
    vals[0] = base;
#pragma unroll
    for (int b = 0; b < B_GRAPHS; b++) vals[b + 1] = dots[b];

#pragma unroll
    for (int k = 0; k < NVALS; k++) {
#pragma unroll
        for (int off = 16; off > 0; off >>= 1)
            vals[k] += __shfl_down_sync(0xFFFFFFFFu, vals[k], off);
    }

    __shared__ float smem[ACC_THREADS / 32][NVALS];
    __shared__ int s_is_last;
    int warp = threadIdx.x >> 5;
    int lane = threadIdx.x & 31;
    if (lane == 0) {
#pragma unroll
        for (int k = 0; k < NVALS; k++) smem[warp][k] = vals[k];
    }
    __syncthreads();

    if (threadIdx.x == 0) {
        float o[NVALS];
#pragma unroll
        for (int k = 0; k < NVALS; k++) o[k] = smem[0][k];
#pragma unroll
        for (int w = 1; w < ACC_THREADS / 32; w++) {
#pragma unroll
            for (int k = 0; k < NVALS; k++) o[k] += smem[w][k];
        }
#pragma unroll
        for (int k = 0; k < NVALS; k++)
            g_partials[k][blockIdx.x] = o[k];

        __threadfence();
        unsigned int ticket = atomicAdd(&g_ticket, 1u);
        s_is_last = (ticket == (unsigned)(gridDim.x - 1)) ? 1 : 0;
    }
    __syncthreads();

    if (!s_is_last) return;

    // ----- last block: reduce all partials -----
    __threadfence();   // acquire side of the ticket handshake
    float fv[NVALS];
#pragma unroll
    for (int k = 0; k < NVALS; k++) fv[k] = 0.0f;

    for (int r = threadIdx.x; r < ACC_BLOCKS; r += ACC_THREADS) {
#pragma unroll
        for (int k = 0; k < NVALS; k++)
            fv[k] += g_partials[k][r];
    }

#pragma unroll
    for (int k = 0; k < NVALS; k++) {
#pragma unroll
        for (int off = 16; off > 0; off >>= 1)
            fv[k] += __shfl_down_sync(0xFFFFFFFFu, fv[k], off);
    }

    __syncthreads();   // smem reuse
    if (lane == 0) {
#pragma unroll
        for (int k = 0; k < NVALS; k++) smem[warp][k] = fv[k];
    }
    __syncthreads();

    if (threadIdx.x == 0) {
        float acc[NVALS];
#pragma unroll
        for (int k = 0; k < NVALS; k++) acc[k] = smem[0][k];
#pragma unroll
        for (int w = 1; w < ACC_THREADS / 32; w++) {
#pragma unroll
            for (int k = 0; k < NVALS; k++) acc[k] += smem[w][k];
        }
        // min over all 2^B sign combos == base - 2 * sum_b |dot_b|
        float s = 0.0f;
#pragma unroll
        for (int b = 0; b < B_GRAPHS; b++) s += fabsf(acc[b + 1]);
        out[0] = acc[0] - 2.0f * s;
        g_ticket = 0u;   // reset for next graph replay
    }
}

extern "C" void kernel_launch(void* const* d_in, const int* in_sizes, int n_in,
                              void* d_out, int out_size)
{
    const float* inp   = (const float*)d_in[0];
    const float* tgt   = (const float*)d_in[1];
    const int*   batch = (const int*)d_in[2];
    float* out = (float*)d_out;

    int n = in_sizes[2];  // number of nodes (batch vector length)

    fused_kernel<<<ACC_BLOCKS, ACC_THREADS>>>(inp, tgt, batch, out, n);
}